// round 9
// baseline (speedup 1.0000x reference)
#include <cuda_runtime.h>
#include <cstdint>

#define NN 50000
#define HH 128
#define GG 512
#define CC 10
#define EMAX 800000
#define TS 132        // padded SMEM row stride (floats)
#define SCAN_B 196    // ceil(NN/256)

// ---------------- scratch (no allocs allowed) ----------------
__device__ __align__(16) float g_dis[NN];
__device__ __align__(16) uint32_t g_Hbf[NN * 64];   // gemm out, bf16x2 (gather target)
__device__ __align__(16) uint32_t g_Bbf[NN * 64];   // agg1 out, bf16x2 (gemm2 input)
__device__ __align__(16) float g_pool[GG * HH];
__device__ float g_cnt[GG];
__device__ int   g_deg[NN];
__device__ int   g_off[NN + 1];
__device__ int   g_cur[NN];
__device__ int   g_csr[EMAX];
__device__ unsigned long long g_tstat[SCAN_B];      // decoupled-lookback status
__device__ int g_ei64;
__device__ int g_b64;

__device__ __forceinline__ float blo(uint32_t v) { return __uint_as_float(v << 16); }
__device__ __forceinline__ float bhi(uint32_t v) { return __uint_as_float(v & 0xffff0000u); }
__device__ __forceinline__ uint32_t pack_bf16(float lo, float hi) {
    uint32_t r;
    asm("cvt.rn.bf16x2.f32 %0, %1, %2;" : "=r"(r) : "f"(hi), "f"(lo));
    return r;
}

// ---------------- critical-path init: deg zero + tile status + dtype detect ----
__global__ void init_deg_kernel(const unsigned* __restrict__ ei,
                                const unsigned* __restrict__ bat) {
    int i = blockIdx.x * blockDim.x + threadIdx.x;
    if (i < NN) g_deg[i] = 0;
    if (i < SCAN_B) g_tstat[i] = 0ULL;
    if (blockIdx.x == 0 && threadIdx.x < 32) {
        unsigned oe = 0, ob = 0;
        int lane = threadIdx.x;
        for (int j = lane; j < 1024; j += 32) {
            oe |= ei[2 * j + 1];
            ob |= bat[2 * j + 1];
        }
#pragma unroll
        for (int off = 16; off; off >>= 1) {
            oe |= __shfl_xor_sync(0xffffffffu, oe, off);
            ob |= __shfl_xor_sync(0xffffffffu, ob, off);
        }
        if (lane == 0) { g_ei64 = (oe == 0u); g_b64 = (ob == 0u); }
    }
}

// off-critical-path init: pool accumulators (side stream, before agg_pool)
__global__ void init_pool_kernel() {
    int i = blockIdx.x * blockDim.x + threadIdx.x;
    if (i < GG * HH) g_pool[i] = 0.0f;
    if (i < GG) g_cnt[i] = 0.0f;
}

// ---------------- degree count: 2 edges/thread, 16B loads ----------------
__global__ void deg_kernel(const void* __restrict__ ei, int E) {
    int e0 = (blockIdx.x * blockDim.x + threadIdx.x) * 2;
    if (e0 >= E) return;
    if (g_ei64) {
        const longlong2* dp = (const longlong2*)((const long long*)ei + E);
        longlong2 v = __ldg(dp + (e0 >> 1));
        atomicAdd(&g_deg[(int)v.x], 1);
        if (e0 + 1 < E) atomicAdd(&g_deg[(int)v.y], 1);
    } else {
        const int2* dp = (const int2*)((const int*)ei + E);
        int2 v = __ldg(dp + (e0 >> 1));
        atomicAdd(&g_deg[v.x], 1);
        if (e0 + 1 < E) atomicAdd(&g_deg[v.y], 1);
    }
}

// ---------------------------------------------------------------------------
// Single-pass decoupled-lookback exclusive scan of g_deg.
// ---------------------------------------------------------------------------
__global__ void scan_lookback_kernel() {
    __shared__ int ws[8];
    __shared__ unsigned sexc;
    int bid = blockIdx.x;
    int i = bid * 256 + threadIdx.x;
    int lane = threadIdx.x & 31, wid = threadIdx.x >> 5;
    int d = (i < NN) ? g_deg[i] : 0;
    int incl = d;
#pragma unroll
    for (int off = 1; off < 32; off <<= 1) {
        int u = __shfl_up_sync(0xffffffffu, incl, off);
        if (lane >= off) incl += u;
    }
    if (lane == 31) ws[wid] = incl;
    __syncthreads();
    int wpre = 0, btotal = 0;
#pragma unroll
    for (int w = 0; w < 8; w++) {
        wpre += (w < wid) ? ws[w] : 0;
        btotal += ws[w];
    }

    if (wid == 0) {
        if (bid > 0 && lane == 0)
            atomicExch(&g_tstat[bid], (1ULL << 32) | (unsigned)btotal);
        unsigned exc = 0;
        if (bid > 0) {
            int t = bid - 1;
            while (true) {
                int idx = t - lane;
                unsigned long long st = (idx >= 0)
                    ? atomicAdd(&g_tstat[idx], 0ULL) : (2ULL << 32);
                unsigned flag = (unsigned)(st >> 32);
                unsigned val = (unsigned)st;
                unsigned pmask = __ballot_sync(0xffffffffu, flag == 2u);
                unsigned imask = __ballot_sync(0xffffffffu, flag == 0u);
                if (pmask) {
                    int pl = __ffs(pmask) - 1;
                    if (imask & ((1u << pl) - 1u)) continue;
                    unsigned c = (lane <= (unsigned)pl) ? val : 0u;
#pragma unroll
                    for (int off = 16; off; off >>= 1)
                        c += __shfl_xor_sync(0xffffffffu, c, off);
                    exc += c;
                    break;
                } else {
                    if (imask) continue;
                    unsigned c = val;
#pragma unroll
                    for (int off = 16; off; off >>= 1)
                        c += __shfl_xor_sync(0xffffffffu, c, off);
                    exc += c;
                    t -= 32;
                }
            }
        }
        if (lane == 0) {
            atomicExch(&g_tstat[bid], (2ULL << 32) | (unsigned)(exc + btotal));
            sexc = exc;
        }
    }
    __syncthreads();
    int off0 = (int)sexc + wpre + incl - d;
    if (i < NN) {
        g_off[i] = off0;
        g_cur[i] = off0;
        g_dis[i] = rsqrtf((float)d + 1.0f);
        if (i == NN - 1) g_off[NN] = off0 + d;
    }
}

// ---------------- CSR fill: 2 edges/thread, 16B loads ----------------
__global__ void fill_kernel(const void* __restrict__ ei, int E) {
    int e0 = (blockIdx.x * blockDim.x + threadIdx.x) * 2;
    if (e0 >= E) return;
    int s0, s1, d0, d1;
    bool two = (e0 + 1 < E);
    if (g_ei64) {
        const longlong2* sp = (const longlong2*)(const long long*)ei;
        const longlong2* dp = (const longlong2*)((const long long*)ei + E);
        longlong2 sv = __ldg(sp + (e0 >> 1));
        longlong2 dv = __ldg(dp + (e0 >> 1));
        s0 = (int)sv.x; s1 = (int)sv.y; d0 = (int)dv.x; d1 = (int)dv.y;
    } else {
        const int2* sp = (const int2*)(const int*)ei;
        const int2* dp = (const int2*)((const int*)ei + E);
        int2 sv = __ldg(sp + (e0 >> 1));
        int2 dv = __ldg(dp + (e0 >> 1));
        s0 = sv.x; s1 = sv.y; d0 = dv.x; d1 = dv.y;
    }
    int slot0 = atomicAdd(&g_cur[d0], 1);
    g_csr[slot0] = s0;
    if (two) {
        int slot1 = atomicAdd(&g_cur[d1], 1);
        g_csr[slot1] = s1;
    }
}

// ---------------------------------------------------------------------------
// tf32 HMMA GEMM: out_bf16[128-row tile][128] = X @ W, K=128.
// BF16IN: X is bf16x2-packed (values exactly representable in tf32).
// ---------------------------------------------------------------------------
__device__ __forceinline__ float to_tf32(float f) {
    uint32_t o;
    asm("cvt.rna.tf32.f32 %0, %1;" : "=r"(o) : "f"(f));
    return __uint_as_float(o);
}

template <bool BF16IN>
__global__ void __launch_bounds__(256, 1)
gemm_mma(const void* __restrict__ Xv, const float* __restrict__ W,
         uint32_t* __restrict__ outb) {
    extern __shared__ float sm[];
    float* Xs = sm;              // 128 x TS
    float* Ws = sm + 128 * TS;   // 128 x TS
    int tid = threadIdx.x;
    int r0 = blockIdx.x * 128;

#pragma unroll
    for (int j = 0; j < 16; j++) {
        int f = tid + j * 256;
        int row = f >> 5, c4 = f & 31;
        int gr = r0 + row;
        float4 v = make_float4(0.f, 0.f, 0.f, 0.f);
        if (gr < NN) {
            if (BF16IN) {
                uint2 u = __ldg((const uint2*)Xv + gr * 32 + c4);
                v.x = blo(u.x); v.y = bhi(u.x);
                v.z = blo(u.y); v.w = bhi(u.y);
                // bf16 values are exact in tf32: no cvt needed
            } else {
                v = __ldg((const float4*)Xv + gr * 32 + c4);
                v.x = to_tf32(v.x); v.y = to_tf32(v.y);
                v.z = to_tf32(v.z); v.w = to_tf32(v.w);
            }
        }
        *(float4*)(Xs + row * TS + c4 * 4) = v;
        float4 w = ((const float4*)W)[row * 32 + c4];
        w.x = to_tf32(w.x); w.y = to_tf32(w.y);
        w.z = to_tf32(w.z); w.w = to_tf32(w.w);
        *(float4*)(Ws + row * TS + c4 * 4) = w;
    }
    __syncthreads();

    int lane = tid & 31, wid = tid >> 5;
    int mw = (wid >> 1) * 32;
    int nw = (wid & 1) * 64;
    int gq = lane >> 2;
    int tq = lane & 3;

    float acc[2][8][4];
#pragma unroll
    for (int m = 0; m < 2; m++)
#pragma unroll
        for (int n = 0; n < 8; n++)
#pragma unroll
            for (int q = 0; q < 4; q++) acc[m][n][q] = 0.f;

#pragma unroll
    for (int kt = 0; kt < 16; kt++) {
        int k0 = kt * 8;
        uint32_t b0[8], b1[8];
        const float* wrow0 = Ws + (k0 + tq) * TS + nw + gq;
        const float* wrow1 = wrow0 + 4 * TS;
#pragma unroll
        for (int n = 0; n < 8; n++) {
            b0[n] = __float_as_uint(wrow0[n * 8]);
            b1[n] = __float_as_uint(wrow1[n * 8]);
        }
        uint32_t a[2][4];
#pragma unroll
        for (int m = 0; m < 2; m++) {
            const float* xr = Xs + (mw + m * 16 + gq) * TS + k0 + tq;
            a[m][0] = __float_as_uint(xr[0]);
            a[m][1] = __float_as_uint(xr[8 * TS]);
            a[m][2] = __float_as_uint(xr[4]);
            a[m][3] = __float_as_uint(xr[8 * TS + 4]);
        }
#pragma unroll
        for (int m = 0; m < 2; m++)
#pragma unroll
            for (int n = 0; n < 8; n++)
                asm volatile(
                    "mma.sync.aligned.m16n8k8.row.col.f32.tf32.tf32.f32 "
                    "{%0,%1,%2,%3}, {%4,%5,%6,%7}, {%8,%9}, {%0,%1,%2,%3};"
                    : "+f"(acc[m][n][0]), "+f"(acc[m][n][1]),
                      "+f"(acc[m][n][2]), "+f"(acc[m][n][3])
                    : "r"(a[m][0]), "r"(a[m][1]), "r"(a[m][2]), "r"(a[m][3]),
                      "r"(b0[n]), "r"(b1[n]));
    }

#pragma unroll
    for (int m = 0; m < 2; m++) {
        int r = r0 + mw + m * 16 + gq;
#pragma unroll
        for (int n = 0; n < 8; n++) {
            int cp = (nw >> 1) + n * 4 + tq;     // bf16x2 column index
            if (r < NN)
                outb[r * 64 + cp] = pack_bf16(acc[m][n][0], acc[m][n][1]);
            if (r + 8 < NN)
                outb[(r + 8) * 64 + cp] = pack_bf16(acc[m][n][2], acc[m][n][3]);
        }
    }
}

// ---------------- CSR aggregation core (bf16 gather, fp32 accumulate) ----------
__device__ __forceinline__ float4 agg_row(const uint32_t* __restrict__ hb,
                                          const float* __restrict__ bias,
                                          int w, int lane) {
    float dd = g_dis[w];
    float sc = dd * dd;
    uint2 sv = __ldg((const uint2*)hb + w * 32 + lane);
    float4 acc;
    acc.x = blo(sv.x) * sc;
    acc.y = bhi(sv.x) * sc;
    acc.z = blo(sv.y) * sc;
    acc.w = bhi(sv.y) * sc;
    int beg = g_off[w], end = g_off[w + 1];
    int s0 = (beg < end) ? g_csr[beg] : 0;
    int s1 = (beg + 1 < end) ? g_csr[beg + 1] : 0;
    for (int e = beg; e < end; e++) {
        int s = s0;
        s0 = s1;
        s1 = (e + 2 < end) ? g_csr[e + 2] : 0;
        float nr = g_dis[s] * dd;
        uint2 pv = __ldg((const uint2*)hb + s * 32 + lane);
        acc.x = fmaf(blo(pv.x), nr, acc.x);
        acc.y = fmaf(bhi(pv.x), nr, acc.y);
        acc.z = fmaf(blo(pv.y), nr, acc.z);
        acc.w = fmaf(bhi(pv.y), nr, acc.w);
    }
    int c = lane * 4;
    acc.x = fmaxf(acc.x + __ldg(bias + c + 0), 0.f);
    acc.y = fmaxf(acc.y + __ldg(bias + c + 1), 0.f);
    acc.z = fmaxf(acc.z + __ldg(bias + c + 2), 0.f);
    acc.w = fmaxf(acc.w + __ldg(bias + c + 3), 0.f);
    return acc;
}

// layer-1 agg: writes bf16x2 (gemm2 input)
__global__ void agg_kernel(const uint32_t* __restrict__ hb,
                           const float* __restrict__ bias,
                           uint32_t* __restrict__ outb) {
    int w = (blockIdx.x * blockDim.x + threadIdx.x) >> 5;
    int lane = threadIdx.x & 31;
    if (w >= NN) return;
    float4 acc = agg_row(hb, bias, w, lane);
    uint2 pk;
    pk.x = pack_bf16(acc.x, acc.y);
    pk.y = pack_bf16(acc.z, acc.w);
    ((uint2*)outb)[w * 32 + lane] = pk;
}

// layer-2 agg fused with mean-pool accumulation: never materializes h2
__global__ void agg_pool_kernel(const uint32_t* __restrict__ hb,
                                const float* __restrict__ bias,
                                const void* __restrict__ bat) {
    int w = (blockIdx.x * blockDim.x + threadIdx.x) >> 5;
    int lane = threadIdx.x & 31;
    if (w >= NN) return;
    float4 acc = agg_row(hb, bias, w, lane);
    int b = g_b64 ? (int)((const long long*)bat)[w] : ((const int*)bat)[w];
    float* p = g_pool + b * HH + lane * 4;
    asm volatile("red.global.add.v4.f32 [%0], {%1,%2,%3,%4};"
                 :: "l"(p), "f"(acc.x), "f"(acc.y), "f"(acc.z), "f"(acc.w)
                 : "memory");
    if (lane == 0) atomicAdd(&g_cnt[b], 1.0f);
}

__global__ void final_kernel(const float* __restrict__ Wl,
                             const float* __restrict__ bl,
                             float* __restrict__ out) {
    int g = blockIdx.x;
    int lane = threadIdx.x;
    float c = fmaxf(g_cnt[g], 1.0f);
    float inv = 1.0f / c;
    float4 p = ((const float4*)g_pool)[g * 32 + lane];
    p.x *= inv; p.y *= inv; p.z *= inv; p.w *= inv;
    int r = lane * 4;
#pragma unroll
    for (int j = 0; j < CC; j++) {
        float s = p.x * __ldg(Wl + (r + 0) * CC + j)
                + p.y * __ldg(Wl + (r + 1) * CC + j)
                + p.z * __ldg(Wl + (r + 2) * CC + j)
                + p.w * __ldg(Wl + (r + 3) * CC + j);
#pragma unroll
        for (int off = 16; off; off >>= 1)
            s += __shfl_xor_sync(0xffffffffu, s, off);
        if (lane == 0) out[g * CC + j] = s + __ldg(bl + j);
    }
}

extern "C" void kernel_launch(void* const* d_in, const int* in_sizes, int n_in,
                              void* d_out, int out_size) {
    const float* x  = (const float*)d_in[0];
    const void*  ei = d_in[1];
    const void*  bat = d_in[2];
    const float* W1 = (const float*)d_in[3];
    const float* b1 = (const float*)d_in[4];
    const float* W2 = (const float*)d_in[5];
    const float* b2 = (const float*)d_in[6];
    const float* Wl = (const float*)d_in[7];
    const float* bl = (const float*)d_in[8];
    float* out = (float*)d_out;
    int E = in_sizes[1] / 2;

    const int SMEM_GEMM = 2 * 128 * TS * 4;   // 135168 B
    static cudaStream_t s2;
    static cudaEvent_t ev_fork, ev_join;
    static int once = 0;
    if (!once) {
        cudaFuncSetAttribute(gemm_mma<false>,
                             cudaFuncAttributeMaxDynamicSharedMemorySize, SMEM_GEMM);
        cudaFuncSetAttribute(gemm_mma<true>,
                             cudaFuncAttributeMaxDynamicSharedMemorySize, SMEM_GEMM);
        cudaStreamCreateWithFlags(&s2, cudaStreamNonBlocking);
        cudaEventCreateWithFlags(&ev_fork, cudaEventDisableTiming);
        cudaEventCreateWithFlags(&ev_join, cudaEventDisableTiming);
        once = 1;
    }

    uint32_t *Hb, *Bb;
    cudaGetSymbolAddress((void**)&Hb, g_Hbf);
    cudaGetSymbolAddress((void**)&Bb, g_Bbf);

    int eb2 = ((E + 1) / 2 + 255) / 256;      // 2 edges per thread
    int nb32 = (NN * 32 + 255) / 256;
    int gb = (NN + 127) / 128;

    // fork: GEMM1 + pool-zeroing (inputs only) parallel to the CSR-build chain
    cudaEventRecord(ev_fork, 0);
    cudaStreamWaitEvent(s2, ev_fork, 0);
    gemm_mma<false><<<gb, 256, SMEM_GEMM, s2>>>(x, W1, Hb);
    init_pool_kernel<<<257, 256, 0, s2>>>();
    cudaEventRecord(ev_join, s2);

    init_deg_kernel<<<SCAN_B, 256>>>((const unsigned*)ei, (const unsigned*)bat);
    deg_kernel<<<eb2, 256>>>(ei, E);
    scan_lookback_kernel<<<SCAN_B, 256>>>();
    fill_kernel<<<eb2, 256>>>(ei, E);

    cudaStreamWaitEvent(0, ev_join, 0);       // join before agg1
    agg_kernel<<<nb32, 256>>>(Hb, b1, Bb);
    gemm_mma<true><<<gb, 256, SMEM_GEMM>>>(Bb, W2, Hb);
    agg_pool_kernel<<<nb32, 256>>>(Hb, b2, bat);
    final_kernel<<<GG, 32>>>(Wl, bl, out);
}

// round 10
// speedup vs baseline: 1.1150x; 1.1150x over previous
#include <cuda_runtime.h>
#include <cstdint>

#define NN 50000
#define HH 128
#define GG 512
#define CC 10
#define CAP 128       // padded CSR row capacity (max degree headroom)
#define TS 132        // padded SMEM row stride (floats)

// ---------------- scratch (no allocs allowed) ----------------
__device__ __align__(16) float g_dis[NN];
__device__ __align__(16) uint32_t g_Hbf[NN * 64];   // gemm out, bf16x2 (gather target)
__device__ __align__(16) float g_B[NN * HH];        // fp32 intermediate
__device__ __align__(16) float g_pool[GG * HH];
__device__ float g_cnt[GG];
__device__ int   g_deg[NN];
__device__ __align__(16) int g_csr[NN * CAP];       // padded CSR rows
__device__ int g_ei64;
__device__ int g_b64;

__device__ __forceinline__ float blo(uint32_t v) { return __uint_as_float(v << 16); }
__device__ __forceinline__ float bhi(uint32_t v) { return __uint_as_float(v & 0xffff0000u); }
__device__ __forceinline__ uint32_t pack_bf16(float lo, float hi) {
    uint32_t r;
    asm("cvt.rn.bf16x2.f32 %0, %1, %2;" : "=r"(r) : "f"(hi), "f"(lo));
    return r;
}

// ---------------- critical-path init: deg zero + dtype detect ----------------
__global__ void init_deg_kernel(const unsigned* __restrict__ ei,
                                const unsigned* __restrict__ bat) {
    int i = blockIdx.x * blockDim.x + threadIdx.x;
    if (i < NN) g_deg[i] = 0;
    if (blockIdx.x == 0 && threadIdx.x < 32) {
        unsigned oe = 0, ob = 0;
        int lane = threadIdx.x;
        for (int j = lane; j < 1024; j += 32) {
            oe |= ei[2 * j + 1];
            ob |= bat[2 * j + 1];
        }
#pragma unroll
        for (int off = 16; off; off >>= 1) {
            oe |= __shfl_xor_sync(0xffffffffu, oe, off);
            ob |= __shfl_xor_sync(0xffffffffu, ob, off);
        }
        if (lane == 0) { g_ei64 = (oe == 0u); g_b64 = (ob == 0u); }
    }
}

// off-critical-path init: pool accumulators (side stream, before agg_pool)
__global__ void init_pool_kernel() {
    int i = blockIdx.x * blockDim.x + threadIdx.x;
    if (i < GG * HH) g_pool[i] = 0.0f;
    if (i < GG) g_cnt[i] = 0.0f;
}

// ---------------- single-pass padded-CSR fill (deg counted in place) ----------
__global__ void fill_direct_kernel(const void* __restrict__ ei, int E) {
    int e = blockIdx.x * blockDim.x + threadIdx.x;
    if (e >= E) return;
    int src, dst;
    if (g_ei64) {
        src = (int)((const long long*)ei)[e];
        dst = (int)((const long long*)ei)[E + e];
    } else {
        src = ((const int*)ei)[e];
        dst = ((const int*)ei)[E + e];
    }
    int slot = atomicAdd(&g_deg[dst], 1);
    g_csr[dst * CAP + slot] = src;
}

__global__ void dis_kernel() {
    int i = blockIdx.x * blockDim.x + threadIdx.x;
    if (i < NN) g_dis[i] = rsqrtf((float)g_deg[i] + 1.0f);
}

// ---------------------------------------------------------------------------
// tf32 HMMA GEMM: out_bf16[128-row tile][128] = X @ W, K=128.
// ---------------------------------------------------------------------------
__device__ __forceinline__ float to_tf32(float f) {
    uint32_t o;
    asm("cvt.rna.tf32.f32 %0, %1;" : "=r"(o) : "f"(f));
    return __uint_as_float(o);
}

__global__ void __launch_bounds__(256, 1)
gemm_mma(const float* __restrict__ X, const float* __restrict__ W,
         uint32_t* __restrict__ outb) {
    extern __shared__ float sm[];
    float* Xs = sm;              // 128 x TS
    float* Ws = sm + 128 * TS;   // 128 x TS
    int tid = threadIdx.x;
    int r0 = blockIdx.x * 128;

#pragma unroll
    for (int j = 0; j < 16; j++) {
        int f = tid + j * 256;
        int row = f >> 5, c4 = f & 31;
        int gr = r0 + row;
        float4 v = make_float4(0.f, 0.f, 0.f, 0.f);
        if (gr < NN) v = __ldg((const float4*)X + gr * 32 + c4);
        v.x = to_tf32(v.x); v.y = to_tf32(v.y);
        v.z = to_tf32(v.z); v.w = to_tf32(v.w);
        *(float4*)(Xs + row * TS + c4 * 4) = v;
        float4 w = ((const float4*)W)[row * 32 + c4];
        w.x = to_tf32(w.x); w.y = to_tf32(w.y);
        w.z = to_tf32(w.z); w.w = to_tf32(w.w);
        *(float4*)(Ws + row * TS + c4 * 4) = w;
    }
    __syncthreads();

    int lane = tid & 31, wid = tid >> 5;
    int mw = (wid >> 1) * 32;
    int nw = (wid & 1) * 64;
    int gq = lane >> 2;
    int tq = lane & 3;

    float acc[2][8][4];
#pragma unroll
    for (int m = 0; m < 2; m++)
#pragma unroll
        for (int n = 0; n < 8; n++)
#pragma unroll
            for (int q = 0; q < 4; q++) acc[m][n][q] = 0.f;

#pragma unroll
    for (int kt = 0; kt < 16; kt++) {
        int k0 = kt * 8;
        uint32_t b0[8], b1[8];
        const float* wrow0 = Ws + (k0 + tq) * TS + nw + gq;
        const float* wrow1 = wrow0 + 4 * TS;
#pragma unroll
        for (int n = 0; n < 8; n++) {
            b0[n] = __float_as_uint(wrow0[n * 8]);
            b1[n] = __float_as_uint(wrow1[n * 8]);
        }
        uint32_t a[2][4];
#pragma unroll
        for (int m = 0; m < 2; m++) {
            const float* xr = Xs + (mw + m * 16 + gq) * TS + k0 + tq;
            a[m][0] = __float_as_uint(xr[0]);
            a[m][1] = __float_as_uint(xr[8 * TS]);
            a[m][2] = __float_as_uint(xr[4]);
            a[m][3] = __float_as_uint(xr[8 * TS + 4]);
        }
#pragma unroll
        for (int m = 0; m < 2; m++)
#pragma unroll
            for (int n = 0; n < 8; n++)
                asm volatile(
                    "mma.sync.aligned.m16n8k8.row.col.f32.tf32.tf32.f32 "
                    "{%0,%1,%2,%3}, {%4,%5,%6,%7}, {%8,%9}, {%0,%1,%2,%3};"
                    : "+f"(acc[m][n][0]), "+f"(acc[m][n][1]),
                      "+f"(acc[m][n][2]), "+f"(acc[m][n][3])
                    : "r"(a[m][0]), "r"(a[m][1]), "r"(a[m][2]), "r"(a[m][3]),
                      "r"(b0[n]), "r"(b1[n]));
    }

#pragma unroll
    for (int m = 0; m < 2; m++) {
        int r = r0 + mw + m * 16 + gq;
#pragma unroll
        for (int n = 0; n < 8; n++) {
            int cp = (nw >> 1) + n * 4 + tq;     // bf16x2 column index
            if (r < NN)
                outb[r * 64 + cp] = pack_bf16(acc[m][n][0], acc[m][n][1]);
            if (r + 8 < NN)
                outb[(r + 8) * 64 + cp] = pack_bf16(acc[m][n][2], acc[m][n][3]);
        }
    }
}

// ---------------- padded-CSR aggregation (bf16 gather, fp32 accumulate) --------
__device__ __forceinline__ float4 agg_row(const uint32_t* __restrict__ hb,
                                          const float* __restrict__ bias,
                                          int w, int lane) {
    float dd = g_dis[w];
    float sc = dd * dd;
    uint2 sv = __ldg((const uint2*)hb + w * 32 + lane);
    float4 acc;
    acc.x = blo(sv.x) * sc;
    acc.y = bhi(sv.x) * sc;
    acc.z = blo(sv.y) * sc;
    acc.w = bhi(sv.y) * sc;
    const int* row = g_csr + w * CAP;
    int deg = g_deg[w];
    int s0 = (0 < deg) ? row[0] : 0;
    int s1 = (1 < deg) ? row[1] : 0;
    for (int e = 0; e < deg; e++) {
        int s = s0;
        s0 = s1;
        s1 = (e + 2 < deg) ? row[e + 2] : 0;
        float nr = g_dis[s] * dd;
        uint2 pv = __ldg((const uint2*)hb + s * 32 + lane);
        acc.x = fmaf(blo(pv.x), nr, acc.x);
        acc.y = fmaf(bhi(pv.x), nr, acc.y);
        acc.z = fmaf(blo(pv.y), nr, acc.z);
        acc.w = fmaf(bhi(pv.y), nr, acc.w);
    }
    int c = lane * 4;
    acc.x = fmaxf(acc.x + __ldg(bias + c + 0), 0.f);
    acc.y = fmaxf(acc.y + __ldg(bias + c + 1), 0.f);
    acc.z = fmaxf(acc.z + __ldg(bias + c + 2), 0.f);
    acc.w = fmaxf(acc.w + __ldg(bias + c + 3), 0.f);
    return acc;
}

__global__ void agg_kernel(const uint32_t* __restrict__ hb,
                           const float* __restrict__ bias,
                           float* __restrict__ out) {
    int w = (blockIdx.x * blockDim.x + threadIdx.x) >> 5;
    int lane = threadIdx.x & 31;
    if (w >= NN) return;
    float4 acc = agg_row(hb, bias, w, lane);
    ((float4*)out)[w * 32 + lane] = acc;
}

// layer-2 agg fused with mean-pool accumulation: never materializes h2
__global__ void agg_pool_kernel(const uint32_t* __restrict__ hb,
                                const float* __restrict__ bias,
                                const void* __restrict__ bat) {
    int w = (blockIdx.x * blockDim.x + threadIdx.x) >> 5;
    int lane = threadIdx.x & 31;
    if (w >= NN) return;
    float4 acc = agg_row(hb, bias, w, lane);
    int b = g_b64 ? (int)((const long long*)bat)[w] : ((const int*)bat)[w];
    float* p = g_pool + b * HH + lane * 4;
    asm volatile("red.global.add.v4.f32 [%0], {%1,%2,%3,%4};"
                 :: "l"(p), "f"(acc.x), "f"(acc.y), "f"(acc.z), "f"(acc.w)
                 : "memory");
    if (lane == 0) atomicAdd(&g_cnt[b], 1.0f);
}

__global__ void final_kernel(const float* __restrict__ Wl,
                             const float* __restrict__ bl,
                             float* __restrict__ out) {
    int g = blockIdx.x;
    int lane = threadIdx.x;
    float c = fmaxf(g_cnt[g], 1.0f);
    float inv = 1.0f / c;
    float4 p = ((const float4*)g_pool)[g * 32 + lane];
    p.x *= inv; p.y *= inv; p.z *= inv; p.w *= inv;
    int r = lane * 4;
#pragma unroll
    for (int j = 0; j < CC; j++) {
        float s = p.x * __ldg(Wl + (r + 0) * CC + j)
                + p.y * __ldg(Wl + (r + 1) * CC + j)
                + p.z * __ldg(Wl + (r + 2) * CC + j)
                + p.w * __ldg(Wl + (r + 3) * CC + j);
#pragma unroll
        for (int off = 16; off; off >>= 1)
            s += __shfl_xor_sync(0xffffffffu, s, off);
        if (lane == 0) out[g * CC + j] = s + __ldg(bl + j);
    }
}

extern "C" void kernel_launch(void* const* d_in, const int* in_sizes, int n_in,
                              void* d_out, int out_size) {
    const float* x  = (const float*)d_in[0];
    const void*  ei = d_in[1];
    const void*  bat = d_in[2];
    const float* W1 = (const float*)d_in[3];
    const float* b1 = (const float*)d_in[4];
    const float* W2 = (const float*)d_in[5];
    const float* b2 = (const float*)d_in[6];
    const float* Wl = (const float*)d_in[7];
    const float* bl = (const float*)d_in[8];
    float* out = (float*)d_out;
    int E = in_sizes[1] / 2;

    const int SMEM_GEMM = 2 * 128 * TS * 4;   // 135168 B
    static cudaStream_t s2;
    static cudaEvent_t ev_fork, ev_join;
    static int once = 0;
    if (!once) {
        cudaFuncSetAttribute(gemm_mma, cudaFuncAttributeMaxDynamicSharedMemorySize,
                             SMEM_GEMM);
        cudaStreamCreateWithFlags(&s2, cudaStreamNonBlocking);
        cudaEventCreateWithFlags(&ev_fork, cudaEventDisableTiming);
        cudaEventCreateWithFlags(&ev_join, cudaEventDisableTiming);
        once = 1;
    }

    uint32_t* Hb;
    float* B;
    cudaGetSymbolAddress((void**)&Hb, g_Hbf);
    cudaGetSymbolAddress((void**)&B, g_B);

    int eb = (E + 255) / 256;
    int nb32 = (NN * 32 + 255) / 256;
    int nb = (NN + 255) / 256;
    int gb = (NN + 127) / 128;

    // fork: GEMM1 + pool-zeroing (inputs only) parallel to the CSR-build chain
    cudaEventRecord(ev_fork, 0);
    cudaStreamWaitEvent(s2, ev_fork, 0);
    gemm_mma<<<gb, 256, SMEM_GEMM, s2>>>(x, W1, Hb);
    init_pool_kernel<<<257, 256, 0, s2>>>();
    cudaEventRecord(ev_join, s2);

    init_deg_kernel<<<nb, 256>>>((const unsigned*)ei, (const unsigned*)bat);
    fill_direct_kernel<<<eb, 256>>>(ei, E);
    dis_kernel<<<nb, 256>>>();

    cudaStreamWaitEvent(0, ev_join, 0);       // join before agg1
    agg_kernel<<<nb32, 256>>>(Hb, b1, B);
    gemm_mma<<<gb, 256, SMEM_GEMM>>>(B, W2, Hb);
    agg_pool_kernel<<<nb32, 256>>>(Hb, b2, bat);
    final_kernel<<<GG, 32>>>(Wl, bl, out);
}